// round 2
// baseline (speedup 1.0000x reference)
#include <cuda_runtime.h>

#define K_DIM 2048
#define N_ROWS 65536

struct ExpertParams {
    const float *W1, *b1, *W2, *b2, *W3, *b3;
};

__device__ int g_count[4];
__device__ int g_idx[4 * N_ROWS];

__global__ void reset_kernel() {
    if (threadIdx.x < 4) g_count[threadIdx.x] = 0;
}

// Warp-aggregated partition: group lanes by label, one atomic per (warp, label).
__global__ void partition_kernel(const int* __restrict__ labels, float* __restrict__ out) {
    int i = blockIdx.x * blockDim.x + threadIdx.x;
    if (i >= N_ROWS) return;
    int lane = threadIdx.x & 31;
    int l = labels[i];
    bool valid = (l >= 0 && l < 4);
    int key = valid ? l : 4;
    unsigned mask = __match_any_sync(0xffffffffu, key);
    int leader = __ffs(mask) - 1;
    int rank = __popc(mask & ((1u << lane) - 1u));
    int base = 0;
    if (valid) {
        if (lane == leader) base = atomicAdd(&g_count[l], __popc(mask));
    }
    base = __shfl_sync(0xffffffffu, base, leader);
    if (valid) {
        g_idx[l * N_ROWS + base + rank] = i;
    } else {
        out[i] = 0.0f;  // rows with unknown label stay 0 (matches reference)
    }
}

// Fused 3-layer MLP for one expert over a 64-row gathered tile.
// Layer1: [64,2048]@[2048,H] register-tiled GEMM (8 rows x CPT cols / thread)
// Layer2: [64,H]@[H,H/2] from shared
// Layer3: [64,H/2]@[H/2,1] scalar dot, scatter to out by row index.
template<int H>
__global__ void __launch_bounds__(256, 2) decode_kernel(
    const float* __restrict__ x, float* __restrict__ out,
    ExpertParams P0, ExpertParams P1, int e0)
{
    constexpr int H2   = H / 2;
    constexpr int KB   = 16;   // k-chunk
    constexpr int TM   = 64;   // rows per tile
    constexpr int XPAD = 68;   // padded row-dim for transposed x tile
    constexpr int CPT  = H / 32;   // layer1 cols/thread (4 or 2)
    constexpr int CPT2 = H2 / 32;  // layer2 cols/thread (2 or 1)

    const int e = e0 + blockIdx.y;
    const ExpertParams P = blockIdx.y ? P1 : P0;
    const int count = g_count[e];
    const int m0 = blockIdx.x * TM;
    if (m0 >= count) return;
    const int nrows = min(TM, count - m0);
    const int* idx = g_idx + e * N_ROWS + m0;

    extern __shared__ float sm[];
    float* xs   = sm;                         // [2][KB][XPAD]
    float* ws   = xs + 2 * KB * XPAD;         // [2][KB][H]
    float* h1s  = ws + 2 * KB * H;            // [TM][H+4]
    float* w2s  = h1s + TM * (H + 4);         // [H][H2]
    int*   sidx = (int*)(w2s + H * H2);       // [TM]
    float* h2s  = sm;                         // reuse xs/ws region: [TM][H2+1]

    const int tid = threadIdx.x;
    const int tr  = tid >> 5;   // warp id 0..7  -> row group
    const int tc  = tid & 31;   // lane          -> col group

    if (tid < TM) sidx[tid] = idx[tid < nrows ? tid : 0];
    __syncthreads();

    // x tile loader assignment: thread -> (row, 16B quarter of 64B chunk)
    const int lrow = tid >> 2;
    const int lq   = tid & 3;
    const float* xrow = x + (long)sidx[lrow] * K_DIM + lq * 4;

    float c[8][CPT];
    #pragma unroll
    for (int i = 0; i < 8; i++)
        #pragma unroll
        for (int j = 0; j < CPT; j++) c[i][j] = 0.0f;

    float4 gx, gw0, gw1;

    // ---- preload chunk 0 into buffer 0 ----
    gx  = *(const float4*)(xrow);
    gw0 = *(const float4*)(P.W1 + tid * 4);
    if (H == 128) gw1 = *(const float4*)(P.W1 + 1024 + tid * 4);
    xs[(lq * 4 + 0) * XPAD + lrow] = gx.x;
    xs[(lq * 4 + 1) * XPAD + lrow] = gx.y;
    xs[(lq * 4 + 2) * XPAD + lrow] = gx.z;
    xs[(lq * 4 + 3) * XPAD + lrow] = gx.w;
    *(float4*)(ws + tid * 4) = gw0;
    if (H == 128) *(float4*)(ws + 1024 + tid * 4) = gw1;
    __syncthreads();

    const int KT = K_DIM / KB;  // 128 chunks
    for (int kt = 0; kt < KT; kt++) {
        // prefetch next chunk (global -> regs)
        if (kt + 1 < KT) {
            const int kc = (kt + 1) * KB;
            gx  = *(const float4*)(xrow + kc);
            gw0 = *(const float4*)(P.W1 + kc * H + tid * 4);
            if (H == 128) gw1 = *(const float4*)(P.W1 + kc * H + 1024 + tid * 4);
        }
        // compute current chunk from shared
        const float* xb = xs + (kt & 1) * KB * XPAD;
        const float* wb = ws + (kt & 1) * KB * H;
        #pragma unroll
        for (int kk = 0; kk < KB; kk++) {
            float4 xa = *(const float4*)(xb + kk * XPAD + tr * 8);
            float4 xc = *(const float4*)(xb + kk * XPAD + tr * 8 + 4);
            float xr[8] = {xa.x, xa.y, xa.z, xa.w, xc.x, xc.y, xc.z, xc.w};
            float wr[CPT];
            if (CPT == 4) {
                float4 wv = *(const float4*)(wb + kk * H + tc * 4);
                wr[0] = wv.x; wr[1] = wv.y; wr[2] = wv.z; wr[3] = wv.w;
            } else {
                float2 wv = *(const float2*)(wb + kk * H + tc * 2);
                wr[0] = wv.x; wr[1] = wv.y;
            }
            #pragma unroll
            for (int i = 0; i < 8; i++)
                #pragma unroll
                for (int j = 0; j < CPT; j++)
                    c[i][j] = fmaf(xr[i], wr[j], c[i][j]);
        }
        // stage prefetched regs into the other buffer
        if (kt + 1 < KT) {
            float* xb2 = xs + ((kt + 1) & 1) * KB * XPAD;
            float* wb2 = ws + ((kt + 1) & 1) * KB * H;
            xb2[(lq * 4 + 0) * XPAD + lrow] = gx.x;
            xb2[(lq * 4 + 1) * XPAD + lrow] = gx.y;
            xb2[(lq * 4 + 2) * XPAD + lrow] = gx.z;
            xb2[(lq * 4 + 3) * XPAD + lrow] = gx.w;
            *(float4*)(wb2 + tid * 4) = gw0;
            if (H == 128) *(float4*)(wb2 + 1024 + tid * 4) = gw1;
        }
        __syncthreads();
    }

    // ---- layer 1 epilogue: bias + relu -> h1s ----
    {
        float bb[CPT];
        if (CPT == 4) {
            float4 bv = *(const float4*)(P.b1 + tc * 4);
            bb[0] = bv.x; bb[1] = bv.y; bb[2] = bv.z; bb[3] = bv.w;
        } else {
            float2 bv = *(const float2*)(P.b1 + tc * 2);
            bb[0] = bv.x; bb[1] = bv.y;
        }
        #pragma unroll
        for (int i = 0; i < 8; i++)
            #pragma unroll
            for (int j = 0; j < CPT; j++)
                h1s[(tr * 8 + i) * (H + 4) + tc * CPT + j] = fmaxf(c[i][j] + bb[j], 0.0f);
    }
    // load W2 into shared (contiguous row-major [H][H2])
    for (int o = tid * 4; o < H * H2; o += 1024)
        *(float4*)(w2s + o) = *(const float4*)(P.W2 + o);
    __syncthreads();

    // ---- layer 2: [64,H] @ [H,H2] ----
    float c2[8][CPT2];
    #pragma unroll
    for (int i = 0; i < 8; i++)
        #pragma unroll
        for (int j = 0; j < CPT2; j++) c2[i][j] = 0.0f;

    #pragma unroll 4
    for (int k = 0; k < H; k++) {
        float w2r[CPT2];
        #pragma unroll
        for (int j = 0; j < CPT2; j++) w2r[j] = w2s[k * H2 + tc * CPT2 + j];
        #pragma unroll
        for (int i = 0; i < 8; i++) {
            float xv = h1s[(tr * 8 + i) * (H + 4) + k];
            #pragma unroll
            for (int j = 0; j < CPT2; j++)
                c2[i][j] = fmaf(xv, w2r[j], c2[i][j]);
        }
    }
    // bias + relu -> h2s (reuses xs/ws region; nobody reads that region anymore)
    {
        float b2r[CPT2];
        #pragma unroll
        for (int j = 0; j < CPT2; j++) b2r[j] = __ldg(P.b2 + tc * CPT2 + j);
        #pragma unroll
        for (int i = 0; i < 8; i++)
            #pragma unroll
            for (int j = 0; j < CPT2; j++)
                h2s[(tr * 8 + i) * (H2 + 1) + tc * CPT2 + j] = fmaxf(c2[i][j] + b2r[j], 0.0f);
    }
    __syncthreads();

    // ---- layer 3: dot over H2 + bias, scatter to out ----
    if (tid < nrows) {
        float acc = 0.0f;
        #pragma unroll
        for (int k = 0; k < H2; k++)
            acc = fmaf(h2s[tid * (H2 + 1) + k], __ldg(P.W3 + k), acc);
        out[sidx[tid]] = acc + __ldg(P.b3);
    }
}

static inline int smem_bytes(int H) {
    int H2 = H / 2;
    int floats = 2 * 16 * 68 + 2 * 16 * H + 64 * (H + 4) + H * H2;
    return floats * 4 + 64 * 4;  // + sidx
}

extern "C" void kernel_launch(void* const* d_in, const int* in_sizes, int n_in,
                              void* d_out, int out_size) {
    const float* x      = (const float*)d_in[0];
    const int*   labels = (const int*)d_in[1];
    ExpertParams P[4];
    for (int e = 0; e < 4; e++) {
        const int b = 2 + e * 6;
        P[e].W1 = (const float*)d_in[b + 0];
        P[e].b1 = (const float*)d_in[b + 1];
        P[e].W2 = (const float*)d_in[b + 2];
        P[e].b2 = (const float*)d_in[b + 3];
        P[e].W3 = (const float*)d_in[b + 4];
        P[e].b3 = (const float*)d_in[b + 5];
    }
    float* out = (float*)d_out;

    const int smem64  = smem_bytes(64);   // ~42.8 KB
    const int smem128 = smem_bytes(128);  // ~91.9 KB
    cudaFuncSetAttribute(decode_kernel<64>,  cudaFuncAttributeMaxDynamicSharedMemorySize, smem64);
    cudaFuncSetAttribute(decode_kernel<128>, cudaFuncAttributeMaxDynamicSharedMemorySize, smem128);

    reset_kernel<<<1, 32>>>();
    partition_kernel<<<N_ROWS / 256, 256>>>(labels, out);

    dim3 grid(N_ROWS / 64, 2);  // worst case: one expert owns all rows; empty tiles exit early
    decode_kernel<64> <<<grid, 256, smem64 >>>(x, out, P[0], P[1], 0);
    decode_kernel<128><<<grid, 256, smem128>>>(x, out, P[2], P[3], 2);
}